// round 3
// baseline (speedup 1.0000x reference)
#include <cuda_runtime.h>
#include <math.h>
#include <stdint.h>

#define BB 16
#define SS 1024
#define DD 512
#define NN 2048

#define RCTAS 128
#define RTHREADS 256

// ---------------- device scratch ----------------
__device__ float2 g_ent[(size_t)NN * NN];        // padded CSR entries {val, idx-bits}
__device__ int    g_nnz[NN];
__device__ int    g_rowptr[NN + 1];
__device__ float  g_state0[NN * BB];             // transposed initial state [n][b]
__device__ float  g_drive[(size_t)SS * NN * BB]; // [s][n][b]; overwritten with states
__device__ int    g_step[RCTAS];

// ---------------- helpers ----------------
__device__ __forceinline__ uint32_t tf32q(float v) {
    uint32_t h;
    asm("cvt.rna.tf32.f32 %0, %1;" : "=r"(h) : "f"(v));
    return h;
}
__device__ __forceinline__ void mma_tf32(float* d, const uint32_t* a, const uint32_t* b) {
    asm volatile(
        "mma.sync.aligned.m16n8k8.row.col.f32.tf32.tf32.f32 "
        "{%0,%1,%2,%3}, {%4,%5,%6,%7}, {%8,%9}, {%0,%1,%2,%3};"
        : "+f"(d[0]), "+f"(d[1]), "+f"(d[2]), "+f"(d[3])
        : "r"(a[0]), "r"(a[1]), "r"(a[2]), "r"(a[3]), "r"(b[0]), "r"(b[1]));
}

// ---------------- prep kernels ----------------
__global__ void init_kernel(const float* __restrict__ init_state) {
    int i = blockIdx.x * blockDim.x + threadIdx.x;
    if (i < RCTAS) g_step[i] = 0;
    if (i < NN * BB) {
        int b = i & (BB - 1);
        int n = i >> 4;
        g_state0[i] = init_state[(size_t)b * NN + n];
    }
}

__global__ void count_kernel(const float* __restrict__ W) {
    int gw   = (blockIdx.x * blockDim.x + threadIdx.x) >> 5;
    int lane = threadIdx.x & 31;
    if (gw >= NN) return;
    const float* row = W + (size_t)gw * NN;
    int c = 0;
    for (int m0 = 0; m0 < NN; m0 += 32) {
        float w = row[m0 + lane];
        c += __popc(__ballot_sync(0xffffffffu, w != 0.0f));
    }
    if (lane == 0) g_nnz[gw] = (c + 15) & ~15;  // pad to 16
}

__global__ void scan_kernel() {
    __shared__ int sb[2][NN];
    int t = threadIdx.x;
    sb[0][t] = g_nnz[t];
    sb[0][t + 1024] = g_nnz[t + 1024];
    __syncthreads();
    int cur = 0;
    for (int d = 1; d < NN; d <<= 1) {
        for (int k = t; k < NN; k += 1024) {
            int v = sb[cur][k];
            if (k >= d) v += sb[cur][k - d];
            sb[cur ^ 1][k] = v;
        }
        __syncthreads();
        cur ^= 1;
    }
    if (t == 0) g_rowptr[0] = 0;
    g_rowptr[t + 1] = sb[cur][t];
    g_rowptr[t + 1 + 1024] = sb[cur][t + 1024];
}

__global__ void fill_kernel(const float* __restrict__ W) {
    int gw   = (blockIdx.x * blockDim.x + threadIdx.x) >> 5;
    int lane = threadIdx.x & 31;
    if (gw >= NN) return;
    const float* row = W + (size_t)gw * NN;
    int p = g_rowptr[gw];
    for (int m0 = 0; m0 < NN; m0 += 32) {
        float w = row[m0 + lane];
        unsigned msk = __ballot_sync(0xffffffffu, w != 0.0f);
        if (w != 0.0f) {
            int off = p + __popc(msk & ((1u << lane) - 1u));
            g_ent[off] = make_float2(w, __int_as_float(m0 + lane));
        }
        p += __popc(msk);
    }
    int end = g_rowptr[gw + 1];
    for (int q = p + lane; q < end; q += 32)
        g_ent[q] = make_float2(0.0f, __int_as_float(0));
}

// ---------------- tf32 mma.sync drive GEMM ----------------
// C[M=16384, N=2048] = X@Win^T + FB@Wfb^T via 3xTF32 split.
// CTA 128x128, K-chunk 32, 8 warps (2x4), warp tile 64x32 of m16n8k8 mma.
// Epilogue scatters to g_drive[s][n][b] (m = b*1024 + s).
#define SMP 36                       // padded smem row stride (floats)
#define GEMM_SMEM (4 * 128 * SMP * 4)

__global__ void __launch_bounds__(256) drive_gemm_mma(
    const float* __restrict__ X, const float* __restrict__ FB,
    const float* __restrict__ Win, const float* __restrict__ Wfb)
{
    extern __shared__ uint32_t sm[];
    uint32_t* Ah = sm;
    uint32_t* Al = sm + 128 * SMP;
    uint32_t* Bh = sm + 2 * 128 * SMP;
    uint32_t* Bl = sm + 3 * 128 * SMP;

    int tid  = threadIdx.x;
    int wid  = tid >> 5, lane = tid & 31;
    int gid  = lane >> 2, tig = lane & 3;
    int wm   = wid & 1, wn = wid >> 1;
    int rowBase = blockIdx.y * 128, colBase = blockIdx.x * 128;

    // gmem load mapping: row r = tid>>1, 4 consecutive float4 at half (tid&1)
    int lr = tid >> 1;
    int lh = (tid & 1) * 4;

    const float* Aarr[2] = {X, FB};
    const float* Barr[2] = {Win, Wfb};

    float acc[4][4][4];
#pragma unroll
    for (int i = 0; i < 4; i++)
#pragma unroll
        for (int j = 0; j < 4; j++)
#pragma unroll
            for (int k = 0; k < 4; k++) acc[i][j][k] = 0.0f;

    float4 ra[4], rb[4];
#pragma unroll
    for (int j = 0; j < 4; j++) {   // prologue: chunk 0 (pair 0, kk 0)
        ra[j] = __ldg((const float4*)(X   + (size_t)(rowBase + lr) * DD) + lh + j);
        rb[j] = __ldg((const float4*)(Win + (size_t)(colBase + lr) * DD) + lh + j);
    }

    const int NCHUNK = 32;
    for (int kt = 0; kt < NCHUNK; kt++) {
        __syncthreads();  // previous chunk's MMA reads done
#pragma unroll
        for (int j = 0; j < 4; j++) {
            int c = lh * 4 + j * 4;
            uint32_t* pa = Ah + lr * SMP + c;
            uint32_t* qa = Al + lr * SMP + c;
            uint32_t* pb = Bh + lr * SMP + c;
            uint32_t* qb = Bl + lr * SMP + c;
            float4 a = ra[j], b = rb[j];
            uint32_t h;
            h = tf32q(a.x); pa[0] = h; qa[0] = tf32q(a.x - __uint_as_float(h));
            h = tf32q(a.y); pa[1] = h; qa[1] = tf32q(a.y - __uint_as_float(h));
            h = tf32q(a.z); pa[2] = h; qa[2] = tf32q(a.z - __uint_as_float(h));
            h = tf32q(a.w); pa[3] = h; qa[3] = tf32q(a.w - __uint_as_float(h));
            h = tf32q(b.x); pb[0] = h; qb[0] = tf32q(b.x - __uint_as_float(h));
            h = tf32q(b.y); pb[1] = h; qb[1] = tf32q(b.y - __uint_as_float(h));
            h = tf32q(b.z); pb[2] = h; qb[2] = tf32q(b.z - __uint_as_float(h));
            h = tf32q(b.w); pb[3] = h; qb[3] = tf32q(b.w - __uint_as_float(h));
        }
        __syncthreads();

        if (kt + 1 < NCHUNK) {  // overlap next chunk's gmem loads with MMA
            int nk = kt + 1;
            const float* A  = Aarr[nk >> 4];
            const float* Bm = Barr[nk >> 4];
            int kb = (nk & 15) * 8;
#pragma unroll
            for (int j = 0; j < 4; j++) {
                ra[j] = __ldg((const float4*)(A  + (size_t)(rowBase + lr) * DD) + kb + lh + j);
                rb[j] = __ldg((const float4*)(Bm + (size_t)(colBase + lr) * DD) + kb + lh + j);
            }
        }

#pragma unroll
        for (int ks = 0; ks < 4; ks++) {
            uint32_t ah[4][4], al[4][4], bh[4][2], bl[4][2];
            int c = ks * 8 + tig;
#pragma unroll
            for (int mt = 0; mt < 4; mt++) {
                int r = wm * 64 + mt * 16 + gid;
                ah[mt][0] = Ah[r * SMP + c];
                ah[mt][1] = Ah[(r + 8) * SMP + c];
                ah[mt][2] = Ah[r * SMP + c + 4];
                ah[mt][3] = Ah[(r + 8) * SMP + c + 4];
                al[mt][0] = Al[r * SMP + c];
                al[mt][1] = Al[(r + 8) * SMP + c];
                al[mt][2] = Al[r * SMP + c + 4];
                al[mt][3] = Al[(r + 8) * SMP + c + 4];
            }
#pragma unroll
            for (int nt = 0; nt < 4; nt++) {
                int r = wn * 32 + nt * 8 + gid;
                bh[nt][0] = Bh[r * SMP + c];
                bh[nt][1] = Bh[r * SMP + c + 4];
                bl[nt][0] = Bl[r * SMP + c];
                bl[nt][1] = Bl[r * SMP + c + 4];
            }
#pragma unroll
            for (int mt = 0; mt < 4; mt++)
#pragma unroll
                for (int nt = 0; nt < 4; nt++) {
                    mma_tf32(acc[mt][nt], ah[mt], bh[nt]);
                    mma_tf32(acc[mt][nt], ah[mt], bl[nt]);
                    mma_tf32(acc[mt][nt], al[mt], bh[nt]);
                }
        }
    }

    // epilogue: D[m][n] -> g_drive[s][n][b], m = b*1024 + s
#pragma unroll
    for (int mt = 0; mt < 4; mt++) {
#pragma unroll
        for (int half = 0; half < 2; half++) {
            int m = rowBase + wm * 64 + mt * 16 + gid + half * 8;
            int b = m >> 10, s = m & 1023;
            size_t base = ((size_t)s * NN) * BB + b;
#pragma unroll
            for (int nt = 0; nt < 4; nt++) {
                int n = colBase + wn * 32 + nt * 8 + tig * 2;
                g_drive[base + (size_t)n * BB]       = acc[mt][nt][half * 2];
                g_drive[base + (size_t)(n + 1) * BB] = acc[mt][nt][half * 2 + 1];
            }
        }
    }
}

// ---------------- persistent recurrence ----------------
// 128 CTAs x 256 threads; half-warp = 16 batches of one row. All accesses 64B-coalesced.
// State for step s overwrites g_drive[s] in place.
__global__ void __launch_bounds__(RTHREADS, 1) recur_kernel() {
    int tid  = threadIdx.x;
    int w    = tid >> 5;
    int lane = tid & 31;
    int b    = lane & 15;
    int rsel = lane >> 4;
    int row  = blockIdx.x * (RTHREADS / 16) + w * 2 + rsel;

    int start = g_rowptr[row];
    int len   = g_rowptr[row + 1] - start;   // multiple of 16
    const float2* ent = g_ent + start;

    const float* dprev = g_state0;
    for (int s = 0; s < SS; ++s) {
        float* d = g_drive + (size_t)s * (NN * BB);
        const float* cur = dprev;

        float acc = d[(row << 4) + b];   // drive

        for (int j = 0; j < len; j += 16) {
#pragma unroll
            for (int u = 0; u < 16; u++) {
                float2 e = ent[j + u];
                float sv = __ldcg(cur + ((__float_as_int(e.y) << 4) + b));
                acc = fmaf(e.x, sv, acc);
            }
        }

        d[(row << 4) + b] = tanhf(acc);
        dprev = d;

        __syncthreads();
        if (s + 1 < SS) {
            if (tid < 32) {
                if (tid == 0)
                    asm volatile("st.release.gpu.global.u32 [%0], %1;"
                                 :: "l"(&g_step[blockIdx.x]), "r"(s + 1) : "memory");
                int t = s + 1;
                bool ok;
                do {
                    int v0, v1, v2, v3;
                    asm volatile("ld.acquire.gpu.global.u32 %0, [%1];" : "=r"(v0) : "l"(&g_step[lane])      : "memory");
                    asm volatile("ld.acquire.gpu.global.u32 %0, [%1];" : "=r"(v1) : "l"(&g_step[lane + 32]) : "memory");
                    asm volatile("ld.acquire.gpu.global.u32 %0, [%1];" : "=r"(v2) : "l"(&g_step[lane + 64]) : "memory");
                    asm volatile("ld.acquire.gpu.global.u32 %0, [%1];" : "=r"(v3) : "l"(&g_step[lane + 96]) : "memory");
                    ok = (v0 >= t) && (v1 >= t) && (v2 >= t) && (v3 >= t);
                } while (!__all_sync(0xffffffffu, ok));
            }
            __syncthreads();
        }
    }
}

// ---------------- final transpose: g_drive[s][n][b] -> out[b][s][n] ----------------
#define TSB 8
#define TNB 64
__global__ void __launch_bounds__(256) transpose_kernel(float* __restrict__ out) {
    __shared__ float smt[TSB * TNB * 17];
    int s0 = blockIdx.y * TSB, n0 = blockIdx.x * TNB;
    for (int i = threadIdx.x; i < TSB * TNB * BB; i += 256) {
        int b = i & 15, nl = (i >> 4) & 63, sl = i >> 10;
        smt[(sl * TNB + nl) * 17 + b] =
            g_drive[((size_t)(s0 + sl) * NN + n0 + nl) * BB + b];
    }
    __syncthreads();
    for (int i = threadIdx.x; i < TSB * TNB * BB; i += 256) {
        int nl = i & 63, sl = (i >> 6) & 7, b = i >> 9;
        out[((size_t)b * SS + s0 + sl) * NN + n0 + nl] =
            smt[(sl * TNB + nl) * 17 + b];
    }
}

// ---------------- launch ----------------
extern "C" void kernel_launch(void* const* d_in, const int* in_sizes, int n_in,
                              void* d_out, int out_size) {
    const float* x    = (const float*)d_in[0];
    const float* fb   = (const float*)d_in[1];
    const float* init = (const float*)d_in[2];
    const float* Wres = (const float*)d_in[3];
    const float* Win  = (const float*)d_in[4];
    const float* Wfb  = (const float*)d_in[5];
    float* out = (float*)d_out;

    cudaFuncSetAttribute(drive_gemm_mma, cudaFuncAttributeMaxDynamicSharedMemorySize, GEMM_SMEM);

    init_kernel<<<(NN * BB + 255) / 256, 256>>>(init);
    count_kernel<<<64, 1024>>>(Wres);
    scan_kernel<<<1, 1024>>>();
    fill_kernel<<<64, 1024>>>(Wres);
    drive_gemm_mma<<<dim3(NN / 128, (BB * SS) / 128), 256, GEMM_SMEM>>>(x, fb, Win, Wfb);
    recur_kernel<<<RCTAS, RTHREADS>>>();
    transpose_kernel<<<dim3(NN / TNB, SS / TSB), 256>>>(out);
}

// round 4
// speedup vs baseline: 1.7295x; 1.7295x over previous
#include <cuda_runtime.h>
#include <math.h>
#include <stdint.h>

#define BB 16
#define SS 1024
#define DD 512
#define NN 2048

#define RCTAS 64
#define RTHREADS 512   // 16 warps; each warp: 2 rows x 16 batches

// ---------------- device scratch ----------------
__device__ float2   g_ent[(size_t)NN * NN];        // padded CSR entries {val, idx-bits}
__device__ int      g_nnz[NN];
__device__ int      g_rowptr[NN + 1];
__device__ float    g_state0[NN * BB];             // transposed initial state [n][b]
__device__ float    g_drive[(size_t)SS * NN * BB]; // [s][n][b]; overwritten with states
__device__ unsigned g_cnt;
__device__ unsigned g_flag;

// ---------------- helpers ----------------
__device__ __forceinline__ uint32_t tf32q(float v) {
    uint32_t h;
    asm("cvt.rna.tf32.f32 %0, %1;" : "=r"(h) : "f"(v));
    return h;
}
__device__ __forceinline__ void mma_tf32(float* d, const uint32_t* a, const uint32_t* b) {
    asm volatile(
        "mma.sync.aligned.m16n8k8.row.col.f32.tf32.tf32.f32 "
        "{%0,%1,%2,%3}, {%4,%5,%6,%7}, {%8,%9}, {%0,%1,%2,%3};"
        : "+f"(d[0]), "+f"(d[1]), "+f"(d[2]), "+f"(d[3])
        : "r"(a[0]), "r"(a[1]), "r"(a[2]), "r"(a[3]), "r"(b[0]), "r"(b[1]));
}

// ---------------- prep kernels ----------------
__global__ void init_kernel(const float* __restrict__ init_state) {
    int i = blockIdx.x * blockDim.x + threadIdx.x;
    if (i == 0) { g_cnt = 0u; g_flag = 0u; }
    if (i < NN * BB) {
        int b = i & (BB - 1);
        int n = i >> 4;
        g_state0[i] = init_state[(size_t)b * NN + n];
    }
}

__global__ void count_kernel(const float* __restrict__ W) {
    int gw   = (blockIdx.x * blockDim.x + threadIdx.x) >> 5;
    int lane = threadIdx.x & 31;
    if (gw >= NN) return;
    const float* row = W + (size_t)gw * NN;
    int c = 0;
    for (int m0 = 0; m0 < NN; m0 += 32) {
        float w = row[m0 + lane];
        c += __popc(__ballot_sync(0xffffffffu, w != 0.0f));
    }
    if (lane == 0) g_nnz[gw] = (c + 15) & ~15;  // pad to 16
}

__global__ void scan_kernel() {
    __shared__ int sb[2][NN];
    int t = threadIdx.x;
    sb[0][t] = g_nnz[t];
    sb[0][t + 1024] = g_nnz[t + 1024];
    __syncthreads();
    int cur = 0;
    for (int d = 1; d < NN; d <<= 1) {
        for (int k = t; k < NN; k += 1024) {
            int v = sb[cur][k];
            if (k >= d) v += sb[cur][k - d];
            sb[cur ^ 1][k] = v;
        }
        __syncthreads();
        cur ^= 1;
    }
    if (t == 0) g_rowptr[0] = 0;
    g_rowptr[t + 1] = sb[cur][t];
    g_rowptr[t + 1 + 1024] = sb[cur][t + 1024];
}

__global__ void fill_kernel(const float* __restrict__ W) {
    int gw   = (blockIdx.x * blockDim.x + threadIdx.x) >> 5;
    int lane = threadIdx.x & 31;
    if (gw >= NN) return;
    const float* row = W + (size_t)gw * NN;
    int p = g_rowptr[gw];
    for (int m0 = 0; m0 < NN; m0 += 32) {
        float w = row[m0 + lane];
        unsigned msk = __ballot_sync(0xffffffffu, w != 0.0f);
        if (w != 0.0f) {
            int off = p + __popc(msk & ((1u << lane) - 1u));
            g_ent[off] = make_float2(w, __int_as_float(m0 + lane));
        }
        p += __popc(msk);
    }
    int end = g_rowptr[gw + 1];
    for (int q = p + lane; q < end; q += 32)
        g_ent[q] = make_float2(0.0f, __int_as_float(0));
}

// ---------------- tf32 mma.sync drive GEMM ----------------
// C[M=16384, N=2048] = X@Win^T + FB@Wfb^T via 3xTF32 split.
// CTA 128x128, K-chunk 32, 8 warps (2x4), warp tile 64x32 of m16n8k8 mma.
// Epilogue scatters to g_drive[s][n][b] (m = b*1024 + s).
#define SMP 36
#define GEMM_SMEM (4 * 128 * SMP * 4)

__global__ void __launch_bounds__(256) drive_gemm_mma(
    const float* __restrict__ X, const float* __restrict__ FB,
    const float* __restrict__ Win, const float* __restrict__ Wfb)
{
    extern __shared__ uint32_t sm[];
    uint32_t* Ah = sm;
    uint32_t* Al = sm + 128 * SMP;
    uint32_t* Bh = sm + 2 * 128 * SMP;
    uint32_t* Bl = sm + 3 * 128 * SMP;

    int tid  = threadIdx.x;
    int wid  = tid >> 5, lane = tid & 31;
    int gid  = lane >> 2, tig = lane & 3;
    int wm   = wid & 1, wn = wid >> 1;
    int rowBase = blockIdx.y * 128, colBase = blockIdx.x * 128;

    int lr = tid >> 1;
    int lh = (tid & 1) * 4;

    const float* Aarr[2] = {X, FB};
    const float* Barr[2] = {Win, Wfb};

    float acc[4][4][4];
#pragma unroll
    for (int i = 0; i < 4; i++)
#pragma unroll
        for (int j = 0; j < 4; j++)
#pragma unroll
            for (int k = 0; k < 4; k++) acc[i][j][k] = 0.0f;

    float4 ra[4], rb[4];
#pragma unroll
    for (int j = 0; j < 4; j++) {
        ra[j] = __ldg((const float4*)(X   + (size_t)(rowBase + lr) * DD) + lh + j);
        rb[j] = __ldg((const float4*)(Win + (size_t)(colBase + lr) * DD) + lh + j);
    }

    const int NCHUNK = 32;
    for (int kt = 0; kt < NCHUNK; kt++) {
        __syncthreads();
#pragma unroll
        for (int j = 0; j < 4; j++) {
            int c = lh * 4 + j * 4;
            uint32_t* pa = Ah + lr * SMP + c;
            uint32_t* qa = Al + lr * SMP + c;
            uint32_t* pb = Bh + lr * SMP + c;
            uint32_t* qb = Bl + lr * SMP + c;
            float4 a = ra[j], b = rb[j];
            uint32_t h;
            h = tf32q(a.x); pa[0] = h; qa[0] = tf32q(a.x - __uint_as_float(h));
            h = tf32q(a.y); pa[1] = h; qa[1] = tf32q(a.y - __uint_as_float(h));
            h = tf32q(a.z); pa[2] = h; qa[2] = tf32q(a.z - __uint_as_float(h));
            h = tf32q(a.w); pa[3] = h; qa[3] = tf32q(a.w - __uint_as_float(h));
            h = tf32q(b.x); pb[0] = h; qb[0] = tf32q(b.x - __uint_as_float(h));
            h = tf32q(b.y); pb[1] = h; qb[1] = tf32q(b.y - __uint_as_float(h));
            h = tf32q(b.z); pb[2] = h; qb[2] = tf32q(b.z - __uint_as_float(h));
            h = tf32q(b.w); pb[3] = h; qb[3] = tf32q(b.w - __uint_as_float(h));
        }
        __syncthreads();

        if (kt + 1 < NCHUNK) {
            int nk = kt + 1;
            const float* A  = Aarr[nk >> 4];
            const float* Bm = Barr[nk >> 4];
            int kb = (nk & 15) * 8;
#pragma unroll
            for (int j = 0; j < 4; j++) {
                ra[j] = __ldg((const float4*)(A  + (size_t)(rowBase + lr) * DD) + kb + lh + j);
                rb[j] = __ldg((const float4*)(Bm + (size_t)(colBase + lr) * DD) + kb + lh + j);
            }
        }

#pragma unroll
        for (int ks = 0; ks < 4; ks++) {
            uint32_t ah[4][4], al[4][4], bh[4][2], bl[4][2];
            int c = ks * 8 + tig;
#pragma unroll
            for (int mt = 0; mt < 4; mt++) {
                int r = wm * 64 + mt * 16 + gid;
                ah[mt][0] = Ah[r * SMP + c];
                ah[mt][1] = Ah[(r + 8) * SMP + c];
                ah[mt][2] = Ah[r * SMP + c + 4];
                ah[mt][3] = Ah[(r + 8) * SMP + c + 4];
                al[mt][0] = Al[r * SMP + c];
                al[mt][1] = Al[(r + 8) * SMP + c];
                al[mt][2] = Al[r * SMP + c + 4];
                al[mt][3] = Al[(r + 8) * SMP + c + 4];
            }
#pragma unroll
            for (int nt = 0; nt < 4; nt++) {
                int r = wn * 32 + nt * 8 + gid;
                bh[nt][0] = Bh[r * SMP + c];
                bh[nt][1] = Bh[r * SMP + c + 4];
                bl[nt][0] = Bl[r * SMP + c];
                bl[nt][1] = Bl[r * SMP + c + 4];
            }
#pragma unroll
            for (int mt = 0; mt < 4; mt++)
#pragma unroll
                for (int nt = 0; nt < 4; nt++) {
                    mma_tf32(acc[mt][nt], ah[mt], bh[nt]);
                    mma_tf32(acc[mt][nt], ah[mt], bl[nt]);
                    mma_tf32(acc[mt][nt], al[mt], bh[nt]);
                }
        }
    }

#pragma unroll
    for (int mt = 0; mt < 4; mt++) {
#pragma unroll
        for (int half = 0; half < 2; half++) {
            int m = rowBase + wm * 64 + mt * 16 + gid + half * 8;
            int b = m >> 10, s = m & 1023;
            size_t base = ((size_t)s * NN) * BB + b;
#pragma unroll
            for (int nt = 0; nt < 4; nt++) {
                int n = colBase + wn * 32 + nt * 8 + tig * 2;
                g_drive[base + (size_t)n * BB]       = acc[mt][nt][half * 2];
                g_drive[base + (size_t)(n + 1) * BB] = acc[mt][nt][half * 2 + 1];
            }
        }
    }
}

// ---------------- persistent recurrence ----------------
// 64 CTAs x 512 threads; half-warp = 16 batches of one row. All accesses 64B-coalesced.
// State for step s overwrites g_drive[s] in place.
// Barrier: single counter (acq_rel atomic, one per CTA) + generation flag broadcast.
__global__ void __launch_bounds__(RTHREADS, 1) recur_kernel() {
    int tid  = threadIdx.x;
    int w    = tid >> 5;
    int lane = tid & 31;
    int b    = lane & 15;
    int rsel = lane >> 4;
    int row  = blockIdx.x * (RTHREADS / 16) + w * 2 + rsel;

    int start = g_rowptr[row];
    int len   = g_rowptr[row + 1] - start;   // multiple of 16
    const float2* ent = g_ent + start;

    const float* dprev = g_state0;
    for (int s = 0; s < SS; ++s) {
        float* d = g_drive + (size_t)s * (NN * BB);
        const float* cur = dprev;

        float acc = d[(row << 4) + b];   // drive

        for (int j = 0; j < len; j += 16) {
#pragma unroll
            for (int u = 0; u < 16; u++) {
                float2 e = ent[j + u];
                float sv = __ldcg(cur + ((__float_as_int(e.y) << 4) + b));
                acc = fmaf(e.x, sv, acc);
            }
        }

        d[(row << 4) + b] = tanhf(acc);
        dprev = d;

        __syncthreads();
        if (s + 1 < SS) {
            if (tid == 0) {
                unsigned arr;
                asm volatile("atom.acq_rel.gpu.global.add.u32 %0, [%1], %2;"
                             : "=r"(arr) : "l"(&g_cnt), "r"(1u) : "memory");
                unsigned target = (unsigned)RCTAS * (unsigned)(s + 1);
                if (arr == target - 1u) {
                    asm volatile("st.release.gpu.global.u32 [%0], %1;"
                                 :: "l"(&g_flag), "r"((unsigned)(s + 1)) : "memory");
                } else {
                    unsigned v;
                    do {
                        asm volatile("ld.acquire.gpu.global.u32 %0, [%1];"
                                     : "=r"(v) : "l"(&g_flag) : "memory");
                    } while (v < (unsigned)(s + 1));
                }
            }
            __syncthreads();
        }
    }
}

// ---------------- final transpose: g_drive[s][n][b] -> out[b][s][n] ----------------
#define TSB 8
#define TNB 64
__global__ void __launch_bounds__(256) transpose_kernel(float* __restrict__ out) {
    __shared__ float smt[TSB * TNB * 17];
    int s0 = blockIdx.y * TSB, n0 = blockIdx.x * TNB;
    for (int i = threadIdx.x; i < TSB * TNB * BB; i += 256) {
        int b = i & 15, nl = (i >> 4) & 63, sl = i >> 10;
        smt[(sl * TNB + nl) * 17 + b] =
            g_drive[((size_t)(s0 + sl) * NN + n0 + nl) * BB + b];
    }
    __syncthreads();
    for (int i = threadIdx.x; i < TSB * TNB * BB; i += 256) {
        int nl = i & 63, sl = (i >> 6) & 7, b = i >> 9;
        out[((size_t)b * SS + s0 + sl) * NN + n0 + nl] =
            smt[(sl * TNB + nl) * 17 + b];
    }
}

// ---------------- launch ----------------
extern "C" void kernel_launch(void* const* d_in, const int* in_sizes, int n_in,
                              void* d_out, int out_size) {
    const float* x    = (const float*)d_in[0];
    const float* fb   = (const float*)d_in[1];
    const float* init = (const float*)d_in[2];
    const float* Wres = (const float*)d_in[3];
    const float* Win  = (const float*)d_in[4];
    const float* Wfb  = (const float*)d_in[5];
    float* out = (float*)d_out;

    cudaFuncSetAttribute(drive_gemm_mma, cudaFuncAttributeMaxDynamicSharedMemorySize, GEMM_SMEM);

    init_kernel<<<(NN * BB + 255) / 256, 256>>>(init);
    count_kernel<<<64, 1024>>>(Wres);
    scan_kernel<<<1, 1024>>>();
    fill_kernel<<<64, 1024>>>(Wres);
    drive_gemm_mma<<<dim3(NN / 128, (BB * SS) / 128), 256, GEMM_SMEM>>>(x, fb, Win, Wfb);
    recur_kernel<<<RCTAS, RTHREADS>>>();
    transpose_kernel<<<dim3(NN / TNB, SS / TSB), 256>>>(out);
}